// round 14
// baseline (speedup 1.0000x reference)
#include <cuda_runtime.h>
#include <cuda_bf16.h>
#include <cuda_fp16.h>
#include <cstdint>

#define D 128
#define MAXN 50051
#define MAXE 700000
#define SCAN_B 1024

// ---------------- scratch (no device allocations allowed) ----------------
__device__ __half g_h[(size_t)MAXN * D];    // GEMM out (fp16), UNscaled
__device__ __half g_aggh[(size_t)MAXN * D]; // layer-1 activation (fp16)
__device__ float  g_dinv[MAXN];
__device__ int    g_degi[MAXN];
__device__ int    g_cnt[MAXN];
__device__ int    g_rowptr[MAXN + 1];
__device__ unsigned int g_csr[MAXE];        // (half(dinv[src])<<16) | src
__device__ int    g_bsum[128];
// Idempotent dtype flag (monotone OR of an input-determined predicate).
__device__ int    g_is32 = 0;
// Pre-packed per-lane mma.sync B fragments (validated R6/R7 mapping).
__device__ uint4  g_Wpack[2][16 * 8 * 32];

// ---------------- fused: W pack + histogram zero + dtype detect -------------
__global__ void setup_kernel(const float* __restrict__ W1,
                             const float* __restrict__ W2,
                             const unsigned long long* __restrict__ ei,
                             int N, int nscan, unsigned long long limit) {
    int i = blockIdx.x * blockDim.x + threadIdx.x;

    if (i < N) { g_degi[i] = 0; g_cnt[i] = 0; }

    bool hit = (i < nscan) && (ei[i] >= limit);
    unsigned m = __ballot_sync(0xffffffffu, hit);
    if ((threadIdx.x & 31) == 0 && m) atomicOr(&g_is32, 1);

    if (i < 2 * 16 * 8 * 32) {
        int mm   = i >> 12;
        int rem  = i & 4095;
        int nb   = rem >> 8;
        int kb   = (rem >> 5) & 7;
        int lane = rem & 31;
        int brow = lane >> 2, kq = lane & 3;
        int n  = nb * 8 + brow;
        int k0 = kb * 16 + kq * 2;
        int k1 = k0 + 8;

        const float* W = mm ? W2 : W1;
        float v00 = W[k0 * D + n],       v01 = W[(k0 + 1) * D + n];
        float v10 = W[k1 * D + n],       v11 = W[(k1 + 1) * D + n];

        __nv_bfloat16 h00 = __float2bfloat16(v00), h01 = __float2bfloat16(v01);
        __nv_bfloat16 h10 = __float2bfloat16(v10), h11 = __float2bfloat16(v11);
        __nv_bfloat16 l00 = __float2bfloat16(v00 - __bfloat162float(h00));
        __nv_bfloat16 l01 = __float2bfloat16(v01 - __bfloat162float(h01));
        __nv_bfloat16 l10 = __float2bfloat16(v10 - __bfloat162float(h10));
        __nv_bfloat16 l11 = __float2bfloat16(v11 - __bfloat162float(h11));

        uint4 pk;
        pk.x = ((uint32_t)__bfloat16_as_ushort(h01) << 16) | __bfloat16_as_ushort(h00);
        pk.y = ((uint32_t)__bfloat16_as_ushort(h11) << 16) | __bfloat16_as_ushort(h10);
        pk.z = ((uint32_t)__bfloat16_as_ushort(l01) << 16) | __bfloat16_as_ushort(l00);
        pk.w = ((uint32_t)__bfloat16_as_ushort(l11) << 16) | __bfloat16_as_ushort(l10);
        g_Wpack[mm][(nb * 8 + kb) * 32 + lane] = pk;
    }
}

// ---------------- in-degree histogram (reads dst half only) ----------------
__global__ void hist_kernel(const void* __restrict__ ei, int E) {
    int e = blockIdx.x * blockDim.x + threadIdx.x;
    if (e >= E) return;
    int d = g_is32 ? ((const int*)ei)[E + e]
                   : (int)((const long long*)ei)[E + e];
    atomicAdd(&g_degi[d], 1);
}

// ---------------- per-block inclusive scan (+ dinv); bsum totals ------------
__global__ __launch_bounds__(SCAN_B) void block_scan_kernel(int N) {
    __shared__ int wsum[SCAN_B / 32];
    int tid = threadIdx.x, lane = tid & 31, wid = tid >> 5;
    int i = blockIdx.x * SCAN_B + tid;
    int v = (i < N) ? g_degi[i] : 0;
    int s = v;
#pragma unroll
    for (int o = 1; o < 32; o <<= 1) {
        int t = __shfl_up_sync(0xffffffffu, s, o);
        if (lane >= o) s += t;
    }
    if (lane == 31) wsum[wid] = s;
    __syncthreads();
    if (wid == 0) {
        int ws = wsum[lane];
#pragma unroll
        for (int o = 1; o < 32; o <<= 1) {
            int t = __shfl_up_sync(0xffffffffu, ws, o);
            if (lane >= o) ws += t;
        }
        wsum[lane] = ws;
    }
    __syncthreads();
    int incl = s + (wid > 0 ? wsum[wid - 1] : 0);
    if (i < N) {
        g_rowptr[i + 1] = incl;
        g_dinv[i] = rsqrtf((float)v + 1.0f);
    }
    if (tid == SCAN_B - 1) g_bsum[blockIdx.x] = incl;
}

// ---------------- add block-prefix offsets (warp-reduced) -------------------
__global__ __launch_bounds__(256) void add_off_kernel(int N) {
    __shared__ int s_off;
    int tid = threadIdx.x;
    int i = blockIdx.x * 256 + tid;
    if (tid < 32) {
        int sb = (blockIdx.x * 256) / SCAN_B;
        int v = 0;
        for (int b = tid; b < sb; b += 32) v += g_bsum[b];
#pragma unroll
        for (int o = 16; o; o >>= 1) v += __shfl_down_sync(0xffffffffu, v, o);
        if (tid == 0) s_off = v;
    }
    __syncthreads();
    if (i < N) g_rowptr[i + 1] += s_off;
    if (i == 0) g_rowptr[0] = 0;
}

// ---------------- counting-sort into CSR; pack half(dinv[src]) in hi bits ---
__global__ void csr_fill_kernel(const void* __restrict__ ei, int E) {
    int e = blockIdx.x * blockDim.x + threadIdx.x;
    if (e >= E) return;
    int s, d;
    if (g_is32) {
        const int* p = (const int*)ei;
        s = p[e]; d = p[E + e];
    } else {
        const long long* p = (const long long*)ei;
        s = (int)p[e]; d = (int)p[E + e];
    }
    unsigned short nh = __half_as_ushort(__float2half_rn(g_dinv[s]));
    int pos = g_rowptr[d] + atomicAdd(&g_cnt[d], 1);
    g_csr[pos] = ((unsigned int)nh << 16) | (unsigned int)s;   // s < 65536
}

// ---------------- mma.sync bf16-split GEMM: g_h = fp16(X @ W) ---------------
__device__ __forceinline__ void mma16816(float& c0, float& c1, float& c2, float& c3,
                                         uint32_t a0, uint32_t a1, uint32_t a2, uint32_t a3,
                                         uint32_t b0, uint32_t b1) {
    asm volatile(
        "mma.sync.aligned.m16n8k16.row.col.f32.bf16.bf16.f32 "
        "{%0,%1,%2,%3}, {%4,%5,%6,%7}, {%8,%9}, {%0,%1,%2,%3};"
        : "+f"(c0), "+f"(c1), "+f"(c2), "+f"(c3)
        : "r"(a0), "r"(a1), "r"(a2), "r"(a3), "r"(b0), "r"(b1));
}

__global__ __launch_bounds__(128) void gemm_mma_kernel(
    const float* __restrict__ Xin, int use_agg, int wsel, int N)
{
    __shared__ uint32_t sAh[64][68];
    __shared__ uint32_t sAl[64][68];

    int t = threadIdx.x, wid = t >> 5, lane = t & 31;
    int r0 = blockIdx.x * 64;

#pragma unroll 4
    for (int i = 0; i < 32; i++) {
        int idx = i * 128 + t;
        int row = idx >> 6, w = idx & 63;
        int gr = r0 + row;
        float2 v;
        if (gr >= N)      v = make_float2(0.f, 0.f);
        else if (use_agg) v = __half22float2(*(const __half2*)(g_aggh + (size_t)gr * D + w * 2));
        else              v = *(const float2*)(Xin + (size_t)gr * D + w * 2);
        __nv_bfloat16 h0 = __float2bfloat16(v.x);
        __nv_bfloat16 h1 = __float2bfloat16(v.y);
        __nv_bfloat16 l0 = __float2bfloat16(v.x - __bfloat162float(h0));
        __nv_bfloat16 l1 = __float2bfloat16(v.y - __bfloat162float(h1));
        sAh[row][w] = ((uint32_t)__bfloat16_as_ushort(h1) << 16) | __bfloat16_as_ushort(h0);
        sAl[row][w] = ((uint32_t)__bfloat16_as_ushort(l1) << 16) | __bfloat16_as_ushort(l0);
    }
    __syncthreads();

    int qrow = wid * 16 + (lane >> 2);
    int kq   = lane & 3;
    uint32_t ah[8][4], al[8][4];
#pragma unroll
    for (int kb = 0; kb < 8; kb++) {
        int kw = kb * 8 + kq;
        ah[kb][0] = sAh[qrow][kw];
        ah[kb][1] = sAh[qrow + 8][kw];
        ah[kb][2] = sAh[qrow][kw + 4];
        ah[kb][3] = sAh[qrow + 8][kw + 4];
        al[kb][0] = sAl[qrow][kw];
        al[kb][1] = sAl[qrow + 8][kw];
        al[kb][2] = sAl[qrow][kw + 4];
        al[kb][3] = sAl[qrow + 8][kw + 4];
    }

    int gr0 = r0 + qrow;
    int gr1 = gr0 + 8;
    const uint4* wp = g_Wpack[wsel];

#pragma unroll 2
    for (int nb = 0; nb < 16; nb++) {
        float c0 = 0.f, c1 = 0.f, c2 = 0.f, c3 = 0.f;
        const uint4* wrow = wp + nb * 8 * 32 + lane;
#pragma unroll
        for (int kb = 0; kb < 8; kb++) {
            uint4 b = __ldg(wrow + kb * 32);
            mma16816(c0, c1, c2, c3, ah[kb][0], ah[kb][1], ah[kb][2], ah[kb][3], b.x, b.y);
            mma16816(c0, c1, c2, c3, ah[kb][0], ah[kb][1], ah[kb][2], ah[kb][3], b.z, b.w);
            mma16816(c0, c1, c2, c3, al[kb][0], al[kb][1], al[kb][2], al[kb][3], b.x, b.y);
        }
        int col = nb * 8 + (lane & 3) * 2;
        if (gr0 < N)
            *(__half2*)(&g_h[(size_t)gr0 * D + col]) = __floats2half2_rn(c0, c1);
        if (gr1 < N)
            *(__half2*)(&g_h[(size_t)gr1 * D + col]) = __floats2half2_rn(c2, c3);
    }
}

// ---------------- gather aggregation: 4-deep MLP, per-edge packed norm ------
__device__ __forceinline__ void acc_h4(float4& a, uint2 r, float nrm) {
    float2 p0 = __half22float2(*(const __half2*)&r.x);
    float2 p1 = __half22float2(*(const __half2*)&r.y);
    a.x += p0.x * nrm; a.y += p0.y * nrm; a.z += p1.x * nrm; a.w += p1.y * nrm;
}

__global__ __launch_bounds__(256) void agg_kernel(
    float* __restrict__ out_base, int use_out,
    const float* __restrict__ bias, int N, int do_relu)
{
    int node = (blockIdx.x * blockDim.x + threadIdx.x) >> 5;
    int lane = threadIdx.x & 31;
    if (node >= N) return;

    int beg = g_rowptr[node];
    int end = g_rowptr[node + 1];
    float dn = g_dinv[node];

    const __half* hp = g_h;
    float4 a0 = make_float4(0.f, 0.f, 0.f, 0.f);
    float4 a1 = make_float4(0.f, 0.f, 0.f, 0.f);
    float4 a2 = make_float4(0.f, 0.f, 0.f, 0.f);
    float4 a3 = make_float4(0.f, 0.f, 0.f, 0.f);
    acc_h4(a0, *(const uint2*)(hp + (size_t)node * D + lane * 4), dn);  // self-loop

    for (int j0 = beg; j0 < end; j0 += 32) {
        int jj = j0 + lane;
        unsigned int pj = (jj < end) ? g_csr[jj] : 0u;
        int cnt = min(32, end - j0);
        int k = 0;
        // 4 independent LDG.64s in flight per iteration (MLP = 4)
        for (; k + 3 < cnt; k += 4) {
            unsigned int p0 = __shfl_sync(0xffffffffu, pj, k);
            unsigned int p1 = __shfl_sync(0xffffffffu, pj, k + 1);
            unsigned int p2 = __shfl_sync(0xffffffffu, pj, k + 2);
            unsigned int p3 = __shfl_sync(0xffffffffu, pj, k + 3);
            uint2 r0 = __ldg((const uint2*)(hp + (size_t)(p0 & 0xffffu) * D + lane * 4));
            uint2 r1 = __ldg((const uint2*)(hp + (size_t)(p1 & 0xffffu) * D + lane * 4));
            uint2 r2 = __ldg((const uint2*)(hp + (size_t)(p2 & 0xffffu) * D + lane * 4));
            uint2 r3 = __ldg((const uint2*)(hp + (size_t)(p3 & 0xffffu) * D + lane * 4));
            acc_h4(a0, r0, __half2float(__ushort_as_half((unsigned short)(p0 >> 16))));
            acc_h4(a1, r1, __half2float(__ushort_as_half((unsigned short)(p1 >> 16))));
            acc_h4(a2, r2, __half2float(__ushort_as_half((unsigned short)(p2 >> 16))));
            acc_h4(a3, r3, __half2float(__ushort_as_half((unsigned short)(p3 >> 16))));
        }
        for (; k < cnt; k++) {
            unsigned int p0 = __shfl_sync(0xffffffffu, pj, k);
            uint2 r0 = __ldg((const uint2*)(hp + (size_t)(p0 & 0xffffu) * D + lane * 4));
            acc_h4(a0, r0, __half2float(__ushort_as_half((unsigned short)(p0 >> 16))));
        }
    }
    a0.x += a1.x + a2.x + a3.x;
    a0.y += a1.y + a2.y + a3.y;
    a0.z += a1.z + a2.z + a3.z;
    a0.w += a1.w + a2.w + a3.w;

    float4 b = *(const float4*)(&bias[lane * 4]);
    float4 o;
    o.x = a0.x * dn + b.x;
    o.y = a0.y * dn + b.y;
    o.z = a0.z * dn + b.z;
    o.w = a0.w * dn + b.w;
    if (do_relu) {
        o.x = fmaxf(o.x, 0.f); o.y = fmaxf(o.y, 0.f);
        o.z = fmaxf(o.z, 0.f); o.w = fmaxf(o.w, 0.f);
    }
    if (use_out) {
        *(float4*)(&out_base[(size_t)node * D + lane * 4]) = o;
    } else {
        uint2 pk;
        *(__half2*)&pk.x = __floats2half2_rn(o.x, o.y);
        *(__half2*)&pk.y = __floats2half2_rn(o.z, o.w);
        *(uint2*)(&g_aggh[(size_t)node * D + lane * 4]) = pk;
    }
}

// ---------------- launch: R10 structure (fork-join), agg MLP=4 --------------
extern "C" void kernel_launch(void* const* d_in, const int* in_sizes, int n_in,
                              void* d_out, int out_size) {
    const float* x   = (const float*)d_in[0];
    const void*  ei  = d_in[1];
    const float* W1  = (const float*)d_in[2];
    const float* b1  = (const float*)d_in[3];
    const float* W2  = (const float*)d_in[4];
    const float* b2  = (const float*)d_in[5];
    float*       out = (float*)d_out;

    const int N = in_sizes[0] / D;
    const int E = in_sizes[1] / 2;
    const int nscan = E / 2;

    const int TB = 256;
    const int e_blocks    = (E + TB - 1) / TB;
    const int agg_blocks  = (int)(((long)N * 32 + TB - 1) / TB);
    const int scan_blocks = (N + SCAN_B - 1) / SCAN_B;
    const int mma_blocks  = (N + 63) / 64;
    const int ao_blocks   = (N + TB - 1) / TB;
    int setup_n = N;
    if (nscan > setup_n) setup_n = nscan;
    if (2 * 16 * 8 * 32 > setup_n) setup_n = 2 * 16 * 8 * 32;
    const int setup_blocks = (setup_n + TB - 1) / TB;

    // Host-side only: created during capture, destroyed after; never replayed.
    cudaStream_t side;
    cudaEvent_t evFork, evJoin1;
    cudaStreamCreateWithFlags(&side, cudaStreamNonBlocking);
    cudaEventCreateWithFlags(&evFork, cudaEventDisableTiming);
    cudaEventCreateWithFlags(&evJoin1, cudaEventDisableTiming);

    // ---- setup on main; fork GEMM1 to side; CSR chain on main ----
    setup_kernel<<<setup_blocks, TB>>>(W1, W2, (const unsigned long long*)ei,
                                      N, nscan, (unsigned long long)N);
    cudaEventRecord(evFork, 0);
    cudaStreamWaitEvent(side, evFork, 0);
    gemm_mma_kernel<<<mma_blocks, 128, 0, side>>>(x, 0, 0, N);
    cudaEventRecord(evJoin1, side);

    hist_kernel<<<e_blocks, TB>>>(ei, E);
    block_scan_kernel<<<scan_blocks, SCAN_B>>>(N);
    add_off_kernel<<<ao_blocks, TB>>>(N);
    csr_fill_kernel<<<e_blocks, TB>>>(ei, E);

    // ---- join; layer 1 agg, then layer 2 (serial, full-device kernels) ----
    cudaStreamWaitEvent(0, evJoin1, 0);
    agg_kernel<<<agg_blocks, TB>>>(out, 0, b1, N, 1);
    gemm_mma_kernel<<<mma_blocks, 128>>>(x, 1, 1, N);
    agg_kernel<<<agg_blocks, TB>>>(out, 1, b2, N, 0);

    cudaEventDestroy(evFork);
    cudaEventDestroy(evJoin1);
    cudaStreamDestroy(side);
}

// round 15
// speedup vs baseline: 1.1802x; 1.1802x over previous
#include <cuda_runtime.h>
#include <cuda_bf16.h>
#include <cuda_fp16.h>
#include <cstdint>

#define D 128
#define MAXN 50051
#define MAXE 700000
#define SCAN_B 1024

// ---------------- scratch (no device allocations allowed) ----------------
__device__ __half g_h[(size_t)MAXN * D];    // GEMM out (fp16), UNscaled
__device__ __half g_aggh[(size_t)MAXN * D]; // layer-1 activation (fp16)
__device__ float  g_dinv[MAXN];
__device__ int    g_degi[MAXN];
__device__ int    g_cnt[MAXN];
__device__ int    g_rowptr[MAXN + 1];
__device__ unsigned int g_csr[MAXE];        // (half(dinv[src])<<16) | src
__device__ int    g_bsum[128];
// Idempotent dtype flag (monotone OR of an input-determined predicate).
__device__ int    g_is32 = 0;
// Pre-packed per-lane mma.sync B fragments (validated R6/R7 mapping).
__device__ uint4  g_Wpack[2][16 * 8 * 32];

// ---------------- fused: W pack + histogram zero + dtype detect -------------
__global__ void setup_kernel(const float* __restrict__ W1,
                             const float* __restrict__ W2,
                             const unsigned long long* __restrict__ ei,
                             int N, int nscan, unsigned long long limit) {
    int i = blockIdx.x * blockDim.x + threadIdx.x;

    if (i < N) { g_degi[i] = 0; g_cnt[i] = 0; }

    bool hit = (i < nscan) && (ei[i] >= limit);
    unsigned m = __ballot_sync(0xffffffffu, hit);
    if ((threadIdx.x & 31) == 0 && m) atomicOr(&g_is32, 1);

    if (i < 2 * 16 * 8 * 32) {
        int mm   = i >> 12;
        int rem  = i & 4095;
        int nb   = rem >> 8;
        int kb   = (rem >> 5) & 7;
        int lane = rem & 31;
        int brow = lane >> 2, kq = lane & 3;
        int n  = nb * 8 + brow;
        int k0 = kb * 16 + kq * 2;
        int k1 = k0 + 8;

        const float* W = mm ? W2 : W1;
        float v00 = W[k0 * D + n],       v01 = W[(k0 + 1) * D + n];
        float v10 = W[k1 * D + n],       v11 = W[(k1 + 1) * D + n];

        __nv_bfloat16 h00 = __float2bfloat16(v00), h01 = __float2bfloat16(v01);
        __nv_bfloat16 h10 = __float2bfloat16(v10), h11 = __float2bfloat16(v11);
        __nv_bfloat16 l00 = __float2bfloat16(v00 - __bfloat162float(h00));
        __nv_bfloat16 l01 = __float2bfloat16(v01 - __bfloat162float(h01));
        __nv_bfloat16 l10 = __float2bfloat16(v10 - __bfloat162float(h10));
        __nv_bfloat16 l11 = __float2bfloat16(v11 - __bfloat162float(h11));

        uint4 pk;
        pk.x = ((uint32_t)__bfloat16_as_ushort(h01) << 16) | __bfloat16_as_ushort(h00);
        pk.y = ((uint32_t)__bfloat16_as_ushort(h11) << 16) | __bfloat16_as_ushort(h10);
        pk.z = ((uint32_t)__bfloat16_as_ushort(l01) << 16) | __bfloat16_as_ushort(l00);
        pk.w = ((uint32_t)__bfloat16_as_ushort(l11) << 16) | __bfloat16_as_ushort(l10);
        g_Wpack[mm][(nb * 8 + kb) * 32 + lane] = pk;
    }
}

// ---------------- in-degree histogram (reads dst half only) ----------------
__global__ void hist_kernel(const void* __restrict__ ei, int E) {
    int e = blockIdx.x * blockDim.x + threadIdx.x;
    if (e >= E) return;
    int d = g_is32 ? ((const int*)ei)[E + e]
                   : (int)((const long long*)ei)[E + e];
    atomicAdd(&g_degi[d], 1);
}

// ---------------- per-block inclusive scan (+ dinv); bsum totals ------------
__global__ __launch_bounds__(SCAN_B) void block_scan_kernel(int N) {
    __shared__ int wsum[SCAN_B / 32];
    int tid = threadIdx.x, lane = tid & 31, wid = tid >> 5;
    int i = blockIdx.x * SCAN_B + tid;
    int v = (i < N) ? g_degi[i] : 0;
    int s = v;
#pragma unroll
    for (int o = 1; o < 32; o <<= 1) {
        int t = __shfl_up_sync(0xffffffffu, s, o);
        if (lane >= o) s += t;
    }
    if (lane == 31) wsum[wid] = s;
    __syncthreads();
    if (wid == 0) {
        int ws = wsum[lane];
#pragma unroll
        for (int o = 1; o < 32; o <<= 1) {
            int t = __shfl_up_sync(0xffffffffu, ws, o);
            if (lane >= o) ws += t;
        }
        wsum[lane] = ws;
    }
    __syncthreads();
    int incl = s + (wid > 0 ? wsum[wid - 1] : 0);
    if (i < N) {
        g_rowptr[i + 1] = incl;
        g_dinv[i] = rsqrtf((float)v + 1.0f);
    }
    if (tid == SCAN_B - 1) g_bsum[blockIdx.x] = incl;
}

// ---------------- add block-prefix offsets (warp-reduced) -------------------
__global__ __launch_bounds__(256) void add_off_kernel(int N) {
    __shared__ int s_off;
    int tid = threadIdx.x;
    int i = blockIdx.x * 256 + tid;
    if (tid < 32) {
        int sb = (blockIdx.x * 256) / SCAN_B;
        int v = 0;
        for (int b = tid; b < sb; b += 32) v += g_bsum[b];
#pragma unroll
        for (int o = 16; o; o >>= 1) v += __shfl_down_sync(0xffffffffu, v, o);
        if (tid == 0) s_off = v;
    }
    __syncthreads();
    if (i < N) g_rowptr[i + 1] += s_off;
    if (i == 0) g_rowptr[0] = 0;
}

// ---------------- counting-sort into CSR; pack half(dinv[src]) in hi bits ---
__global__ void csr_fill_kernel(const void* __restrict__ ei, int E) {
    int e = blockIdx.x * blockDim.x + threadIdx.x;
    if (e >= E) return;
    int s, d;
    if (g_is32) {
        const int* p = (const int*)ei;
        s = p[e]; d = p[E + e];
    } else {
        const long long* p = (const long long*)ei;
        s = (int)p[e]; d = (int)p[E + e];
    }
    unsigned short nh = __half_as_ushort(__float2half_rn(g_dinv[s]));
    int pos = g_rowptr[d] + atomicAdd(&g_cnt[d], 1);
    g_csr[pos] = ((unsigned int)nh << 16) | (unsigned int)s;   // s < 65536
}

// ---------------- mma.sync bf16-split GEMM: g_h = fp16(X @ W) ---------------
__device__ __forceinline__ void mma16816(float& c0, float& c1, float& c2, float& c3,
                                         uint32_t a0, uint32_t a1, uint32_t a2, uint32_t a3,
                                         uint32_t b0, uint32_t b1) {
    asm volatile(
        "mma.sync.aligned.m16n8k16.row.col.f32.bf16.bf16.f32 "
        "{%0,%1,%2,%3}, {%4,%5,%6,%7}, {%8,%9}, {%0,%1,%2,%3};"
        : "+f"(c0), "+f"(c1), "+f"(c2), "+f"(c3)
        : "r"(a0), "r"(a1), "r"(a2), "r"(a3), "r"(b0), "r"(b1));
}

__global__ __launch_bounds__(128) void gemm_mma_kernel(
    const float* __restrict__ Xin, int use_agg, int wsel, int N)
{
    __shared__ uint32_t sAh[64][68];
    __shared__ uint32_t sAl[64][68];

    int t = threadIdx.x, wid = t >> 5, lane = t & 31;
    int r0 = blockIdx.x * 64;

#pragma unroll 4
    for (int i = 0; i < 32; i++) {
        int idx = i * 128 + t;
        int row = idx >> 6, w = idx & 63;
        int gr = r0 + row;
        float2 v;
        if (gr >= N)      v = make_float2(0.f, 0.f);
        else if (use_agg) v = __half22float2(*(const __half2*)(g_aggh + (size_t)gr * D + w * 2));
        else              v = *(const float2*)(Xin + (size_t)gr * D + w * 2);
        __nv_bfloat16 h0 = __float2bfloat16(v.x);
        __nv_bfloat16 h1 = __float2bfloat16(v.y);
        __nv_bfloat16 l0 = __float2bfloat16(v.x - __bfloat162float(h0));
        __nv_bfloat16 l1 = __float2bfloat16(v.y - __bfloat162float(h1));
        sAh[row][w] = ((uint32_t)__bfloat16_as_ushort(h1) << 16) | __bfloat16_as_ushort(h0);
        sAl[row][w] = ((uint32_t)__bfloat16_as_ushort(l1) << 16) | __bfloat16_as_ushort(l0);
    }
    __syncthreads();

    int qrow = wid * 16 + (lane >> 2);
    int kq   = lane & 3;
    uint32_t ah[8][4], al[8][4];
#pragma unroll
    for (int kb = 0; kb < 8; kb++) {
        int kw = kb * 8 + kq;
        ah[kb][0] = sAh[qrow][kw];
        ah[kb][1] = sAh[qrow + 8][kw];
        ah[kb][2] = sAh[qrow][kw + 4];
        ah[kb][3] = sAh[qrow + 8][kw + 4];
        al[kb][0] = sAl[qrow][kw];
        al[kb][1] = sAl[qrow + 8][kw];
        al[kb][2] = sAl[qrow][kw + 4];
        al[kb][3] = sAl[qrow + 8][kw + 4];
    }

    int gr0 = r0 + qrow;
    int gr1 = gr0 + 8;
    const uint4* wp = g_Wpack[wsel];

#pragma unroll 2
    for (int nb = 0; nb < 16; nb++) {
        float c0 = 0.f, c1 = 0.f, c2 = 0.f, c3 = 0.f;
        const uint4* wrow = wp + nb * 8 * 32 + lane;
#pragma unroll
        for (int kb = 0; kb < 8; kb++) {
            uint4 b = __ldg(wrow + kb * 32);
            mma16816(c0, c1, c2, c3, ah[kb][0], ah[kb][1], ah[kb][2], ah[kb][3], b.x, b.y);
            mma16816(c0, c1, c2, c3, ah[kb][0], ah[kb][1], ah[kb][2], ah[kb][3], b.z, b.w);
            mma16816(c0, c1, c2, c3, al[kb][0], al[kb][1], al[kb][2], al[kb][3], b.x, b.y);
        }
        int col = nb * 8 + (lane & 3) * 2;
        if (gr0 < N)
            *(__half2*)(&g_h[(size_t)gr0 * D + col]) = __floats2half2_rn(c0, c1);
        if (gr1 < N)
            *(__half2*)(&g_h[(size_t)gr1 * D + col]) = __floats2half2_rn(c2, c3);
    }
}

// ---------------- gather aggregation: per-edge packed norm ------------------
__device__ __forceinline__ void acc_h4(float4& a, uint2 r, float nrm) {
    float2 p0 = __half22float2(*(const __half2*)&r.x);
    float2 p1 = __half22float2(*(const __half2*)&r.y);
    a.x += p0.x * nrm; a.y += p0.y * nrm; a.z += p1.x * nrm; a.w += p1.y * nrm;
}

__global__ __launch_bounds__(256) void agg_kernel(
    float* __restrict__ out_base, int use_out,
    const float* __restrict__ bias, int N, int do_relu)
{
    int node = (blockIdx.x * blockDim.x + threadIdx.x) >> 5;
    int lane = threadIdx.x & 31;
    if (node >= N) return;

    int beg = g_rowptr[node];
    int end = g_rowptr[node + 1];
    float dn = g_dinv[node];

    const __half* hp = g_h;
    float4 a0 = make_float4(0.f, 0.f, 0.f, 0.f);
    float4 a1 = make_float4(0.f, 0.f, 0.f, 0.f);
    acc_h4(a0, *(const uint2*)(hp + (size_t)node * D + lane * 4), dn);  // self-loop

    for (int j0 = beg; j0 < end; j0 += 32) {
        int jj = j0 + lane;
        unsigned int pj = (jj < end) ? g_csr[jj] : 0u;
        int cnt = min(32, end - j0);
        int k = 0;
        for (; k + 1 < cnt; k += 2) {
            unsigned int p0 = __shfl_sync(0xffffffffu, pj, k);
            unsigned int p1 = __shfl_sync(0xffffffffu, pj, k + 1);
            int s0 = (int)(p0 & 0xffffu), s1 = (int)(p1 & 0xffffu);
            float n0 = __half2float(__ushort_as_half((unsigned short)(p0 >> 16)));
            float n1 = __half2float(__ushort_as_half((unsigned short)(p1 >> 16)));
            uint2 r0 = __ldg((const uint2*)(hp + (size_t)s0 * D + lane * 4));
            uint2 r1 = __ldg((const uint2*)(hp + (size_t)s1 * D + lane * 4));
            acc_h4(a0, r0, n0);
            acc_h4(a1, r1, n1);
        }
        if (k < cnt) {
            unsigned int p0 = __shfl_sync(0xffffffffu, pj, k);
            int s0 = (int)(p0 & 0xffffu);
            float n0 = __half2float(__ushort_as_half((unsigned short)(p0 >> 16)));
            acc_h4(a0, __ldg((const uint2*)(hp + (size_t)s0 * D + lane * 4)), n0);
        }
    }
    a0.x += a1.x; a0.y += a1.y; a0.z += a1.z; a0.w += a1.w;

    float4 b = *(const float4*)(&bias[lane * 4]);
    float4 o;
    o.x = a0.x * dn + b.x;
    o.y = a0.y * dn + b.y;
    o.z = a0.z * dn + b.z;
    o.w = a0.w * dn + b.w;
    if (do_relu) {
        o.x = fmaxf(o.x, 0.f); o.y = fmaxf(o.y, 0.f);
        o.z = fmaxf(o.z, 0.f); o.w = fmaxf(o.w, 0.f);
    }
    if (use_out) {
        *(float4*)(&out_base[(size_t)node * D + lane * 4]) = o;
    } else {
        uint2 pk;
        *(__half2*)&pk.x = __floats2half2_rn(o.x, o.y);
        *(__half2*)&pk.y = __floats2half2_rn(o.z, o.w);
        *(uint2*)(&g_aggh[(size_t)node * D + lane * 4]) = pk;
    }
}

// ---------------- launch: fork-join capture (GEMM1 overlaps CSR build) ------
extern "C" void kernel_launch(void* const* d_in, const int* in_sizes, int n_in,
                              void* d_out, int out_size) {
    const float* x   = (const float*)d_in[0];
    const void*  ei  = d_in[1];
    const float* W1  = (const float*)d_in[2];
    const float* b1  = (const float*)d_in[3];
    const float* W2  = (const float*)d_in[4];
    const float* b2  = (const float*)d_in[5];
    float*       out = (float*)d_out;

    const int N = in_sizes[0] / D;
    const int E = in_sizes[1] / 2;
    const int nscan = E / 2;

    const int TB = 256;
    const int e_blocks    = (E + TB - 1) / TB;
    const int agg_blocks  = (int)(((long)N * 32 + TB - 1) / TB);
    const int scan_blocks = (N + SCAN_B - 1) / SCAN_B;
    const int mma_blocks  = (N + 63) / 64;
    const int ao_blocks   = (N + TB - 1) / TB;
    int setup_n = N;
    if (nscan > setup_n) setup_n = nscan;
    if (2 * 16 * 8 * 32 > setup_n) setup_n = 2 * 16 * 8 * 32;
    const int setup_blocks = (setup_n + TB - 1) / TB;

    // Host-side only: created during capture, destroyed after; never replayed.
    cudaStream_t side;
    cudaEvent_t evFork, evJoin1;
    cudaStreamCreateWithFlags(&side, cudaStreamNonBlocking);
    cudaEventCreateWithFlags(&evFork, cudaEventDisableTiming);
    cudaEventCreateWithFlags(&evJoin1, cudaEventDisableTiming);

    // ---- setup on main; fork GEMM1 to side; CSR chain on main ----
    setup_kernel<<<setup_blocks, TB>>>(W1, W2, (const unsigned long long*)ei,
                                      N, nscan, (unsigned long long)N);
    cudaEventRecord(evFork, 0);
    cudaStreamWaitEvent(side, evFork, 0);
    gemm_mma_kernel<<<mma_blocks, 128, 0, side>>>(x, 0, 0, N);
    cudaEventRecord(evJoin1, side);

    hist_kernel<<<e_blocks, TB>>>(ei, E);
    block_scan_kernel<<<scan_blocks, SCAN_B>>>(N);
    add_off_kernel<<<ao_blocks, TB>>>(N);
    csr_fill_kernel<<<e_blocks, TB>>>(ei, E);

    // ---- join; layer 1 agg, then layer 2 (serial, full-device kernels) ----
    cudaStreamWaitEvent(0, evJoin1, 0);
    agg_kernel<<<agg_blocks, TB>>>(out, 0, b1, N, 1);
    gemm_mma_kernel<<<mma_blocks, 128>>>(x, 1, 1, N);
    agg_kernel<<<agg_blocks, TB>>>(out, 1, b2, N, 0);

    cudaEventDestroy(evFork);
    cudaEventDestroy(evJoin1);
    cudaStreamDestroy(side);
}